// round 14
// baseline (speedup 1.0000x reference)
#include <cuda_runtime.h>
#include <cuda_bf16.h>
#include <cuda_fp16.h>
#include <cstdint>

#define N_NODES 32768
#define N_EDGES 65536
#define HID 64
#define LN_EPS 1e-5f

// ---------------- scratch (static device globals; no allocation) ----------------
__device__ float g_sum1[N_NODES * HID];
__device__ float g_sum2[N_NODES * HID];
__device__ float g_cnt[N_NODES];
__device__ float g_h1[N_NODES * HID];
__device__ int   g_src[N_EDGES];
__device__ int   g_dst[N_EDGES];
// layer-2 weights fp16 in FRAGMENT ORDER: g_Wf[k*2048 + nb*256 + lane*8 + s]
// s = c*2 + b01 -> half2( W[k][i=2*ipair][o], W[k][i=2*ipair+1][o] ) with
// ipair = 8c + 4*b01 + (lane&3), o = nb*8 + (lane>>2). k==128 -> bias b2.
__device__ uint32_t g_Wf[129 * 2048];
// layer-1 w2 fp16 fragment order (chunk i = input channel)
__device__ uint32_t g_Wf1[4 * 2048];

__device__ __forceinline__ int clamp_node(long long v) {
    return v < 0 ? 0 : (v >= N_NODES ? N_NODES - 1 : (int)v);
}

__device__ __forceinline__ uint32_t h2_pack(float v0, float v1) {
    __half2 h = __float22half2_rn(make_float2(v0, v1));
    return *reinterpret_cast<uint32_t*>(&h);
}
__device__ __forceinline__ void mma_f16(float* c,
        uint32_t a0, uint32_t a1, uint32_t a2, uint32_t a3,
        uint32_t b0, uint32_t b1) {
    asm volatile(
        "mma.sync.aligned.m16n8k16.row.col.f32.f16.f16.f32 "
        "{%0,%1,%2,%3}, {%4,%5,%6,%7}, {%8,%9}, {%0,%1,%2,%3};\n"
        : "+f"(c[0]), "+f"(c[1]), "+f"(c[2]), "+f"(c[3])
        : "r"(a0), "r"(a1), "r"(a2), "r"(a3), "r"(b0), "r"(b1));
}
__device__ __forceinline__ void mma_f16_zc(float* c,
        uint32_t a0, uint32_t a1, uint32_t a2, uint32_t a3,
        uint32_t b0, uint32_t b1) {
    asm volatile(
        "mma.sync.aligned.m16n8k16.row.col.f32.f16.f16.f32 "
        "{%0,%1,%2,%3}, {%4,%5,%6,%7}, {%8,%9}, {%10,%11,%12,%13};\n"
        : "=f"(c[0]), "=f"(c[1]), "=f"(c[2]), "=f"(c[3])
        : "r"(a0), "r"(a1), "r"(a2), "r"(a3), "r"(b0), "r"(b1),
          "f"(0.f), "f"(0.f), "f"(0.f), "f"(0.f));
}

// ---------------- kernel 0 (fused): zero + edge prep + fragment-order packs ----
#define ZB 8192
#define PB 256
#define SB_BLK 129
#define SB1_BLK 4
__global__ void fused_prep(const void* __restrict__ eidx_raw,
                           const float* __restrict__ w2,    // e2_w2 [128,4096]
                           const float* __restrict__ b2,    // [4096]
                           const float* __restrict__ w2l1,  // e1_w2 [64,256]
                           float* __restrict__ out) {
    int b = blockIdx.x, tid = threadIdx.x;
    if (b < ZB) {
        int idx = b * 256 + tid;
        g_sum1[idx] = 0.f; g_sum2[idx] = 0.f;
        if (idx < N_NODES) g_cnt[idx] = 0.f;
        if (idx < HID) out[idx] = 0.f;
    } else if (b < ZB + PB) {
        const long long* p64 = (const long long*)eidx_raw;
        const int*       p32 = (const int*)eidx_raw;
        bool is64 = true;
#pragma unroll
        for (int i = 0; i < 8; i++) {
            long long v = p64[i];
            if (v < 0 || v >= N_NODES) { is64 = false; break; }
        }
        int e = (b - ZB) * 256 + tid;
        long long s, d;
        if (is64) { s = p64[e]; d = p64[N_EDGES + e]; }
        else      { s = p32[e]; d = p32[N_EDGES + e]; }
        g_src[e] = clamp_node(s);
        g_dst[e] = clamp_node(d);
    } else if (b < ZB + PB + SB_BLK) {
        int k = b - ZB - PB;
        const float* src = (k < 128) ? (w2 + (size_t)k * 4096) : b2;
        int lane = tid & 31;
        int o = ((tid >> 5) * 8) + (lane >> 2);   // nb*8 + lane/4
#pragma unroll
        for (int s = 0; s < 8; s++) {
            int ipair = 8 * (s >> 1) + 4 * (s & 1) + (lane & 3);
            float v0 = __ldg(&src[(2 * ipair) * 64 + o]);
            float v1 = __ldg(&src[(2 * ipair + 1) * 64 + o]);
            g_Wf[(size_t)k * 2048 + tid * 8 + s] = h2_pack(v0, v1);
        }
    } else {
        int i = b - ZB - PB - SB_BLK;             // chunk = input channel 0..3
        int lane = tid & 31;
        int o = ((tid >> 5) * 8) + (lane >> 2);
#pragma unroll
        for (int s = 0; s < 8; s++) {
            int ipair = 8 * (s >> 1) + 4 * (s & 1) + (lane & 3);
            float v0 = __ldg(&w2l1[(2 * ipair) * 256 + i * 64 + o]);
            float v1 = __ldg(&w2l1[(2 * ipair + 1) * 256 + i * 64 + o]);
            g_Wf1[(size_t)i * 2048 + tid * 8 + s] = h2_pack(v0, v1);
        }
    }
}

// ---------------- kernel 1: layer-1 edge pipeline (fragment-LDG) ----------------
__global__ void __launch_bounds__(128, 3) edge_l1_tc(
        const float* __restrict__ x,
        const float* __restrict__ ea,
        const float* __restrict__ w1,   // e1_w1 [4,64]
        const float* __restrict__ b1,   // [64]
        const float* __restrict__ b2) { // [256]
    __shared__ float w1s[256];
    __shared__ float b1s[64];
    __shared__ float b2s[256];

    int tid = threadIdx.x;
    int eb  = blockIdx.x * 128;

    w1s[tid] = __ldg(&w1[tid]);
    w1s[128 + tid] = __ldg(&w1[128 + tid]);
    if (tid < 64) b1s[tid] = __ldg(&b1[tid]);
    b2s[tid] = __ldg(&b2[tid]);
    b2s[128 + tid] = __ldg(&b2[128 + tid]);

    int lane = tid & 31, gID = lane >> 2, tig = lane & 3;
    int wb = (tid >> 5) * 32;
    int er[4] = {wb + gID, wb + 8 + gID, wb + 16 + gID, wb + 24 + gID};

    float4 aev[4];
    float  xsf[4][4];
#pragma unroll
    for (int j = 0; j < 4; j++) {
        aev[j] = __ldg((const float4*)(ea + (size_t)(eb + er[j]) * 4));
        float4 xv = __ldg((const float4*)(x + (size_t)g_src[eb + er[j]] * 4));
        xsf[j][0] = xv.x; xsf[j][1] = xv.y; xsf[j][2] = xv.z; xsf[j][3] = xv.w;
    }
    __syncthreads();

    uint32_t A1[2][4][4];
#pragma unroll
    for (int blk = 0; blk < 2; blk++) {
        float4 eA = aev[blk * 2], eB = aev[blk * 2 + 1];
#pragma unroll
        for (int c = 0; c < 4; c++) {
            int k0 = c * 16 + 2 * tig;
            float hA0, hA1, hA2, hA3, hB0, hB1, hB2, hB3;
#define H1F(a, k) fmaxf(b1s[k] + (a).x * w1s[k] + (a).y * w1s[64 + (k)] \
                        + (a).z * w1s[128 + (k)] + (a).w * w1s[192 + (k)], 0.f)
            hA0 = H1F(eA, k0);     hA1 = H1F(eA, k0 + 1);
            hB0 = H1F(eB, k0);     hB1 = H1F(eB, k0 + 1);
            hA2 = H1F(eA, k0 + 8); hA3 = H1F(eA, k0 + 9);
            hB2 = H1F(eB, k0 + 8); hB3 = H1F(eB, k0 + 9);
#undef H1F
            A1[blk][c][0] = h2_pack(hA0, hA1);
            A1[blk][c][1] = h2_pack(hB0, hB1);
            A1[blk][c][2] = h2_pack(hA2, hA3);
            A1[blk][c][3] = h2_pack(hB2, hB3);
        }
    }

    float acc[2][8][4];
#pragma unroll
    for (int blk = 0; blk < 2; blk++)
#pragma unroll
        for (int nb = 0; nb < 8; nb++)
#pragma unroll
            for (int q = 0; q < 4; q++) acc[blk][nb][q] = 0.f;

#pragma unroll
    for (int i = 0; i < 4; i++) {
        const uint4* Wp = (const uint4*)(g_Wf1 + (size_t)i * 2048) + (lane << 1);
        float hv[4] = {xsf[0][i], xsf[1][i], xsf[2][i], xsf[3][i]};
#pragma unroll
        for (int nb = 0; nb < 8; nb++) {
            uint4 v0 = __ldg(Wp + nb * 64);
            uint4 v1 = __ldg(Wp + nb * 64 + 1);
            float p0[4], p1[4];
            mma_f16_zc(p0, A1[0][0][0], A1[0][0][1], A1[0][0][2], A1[0][0][3], v0.x, v0.y);
            mma_f16(p0, A1[0][1][0], A1[0][1][1], A1[0][1][2], A1[0][1][3], v0.z, v0.w);
            mma_f16(p0, A1[0][2][0], A1[0][2][1], A1[0][2][2], A1[0][2][3], v1.x, v1.y);
            mma_f16(p0, A1[0][3][0], A1[0][3][1], A1[0][3][2], A1[0][3][3], v1.z, v1.w);
            mma_f16_zc(p1, A1[1][0][0], A1[1][0][1], A1[1][0][2], A1[1][0][3], v0.x, v0.y);
            mma_f16(p1, A1[1][1][0], A1[1][1][1], A1[1][1][2], A1[1][1][3], v0.z, v0.w);
            mma_f16(p1, A1[1][2][0], A1[1][2][1], A1[1][2][2], A1[1][2][3], v1.x, v1.y);
            mma_f16(p1, A1[1][3][0], A1[1][3][1], A1[1][3][2], A1[1][3][3], v1.z, v1.w);
            acc[0][nb][0] = fmaf(hv[0], p0[0], acc[0][nb][0]);
            acc[0][nb][1] = fmaf(hv[0], p0[1], acc[0][nb][1]);
            acc[0][nb][2] = fmaf(hv[1], p0[2], acc[0][nb][2]);
            acc[0][nb][3] = fmaf(hv[1], p0[3], acc[0][nb][3]);
            acc[1][nb][0] = fmaf(hv[2], p1[0], acc[1][nb][0]);
            acc[1][nb][1] = fmaf(hv[2], p1[1], acc[1][nb][1]);
            acc[1][nb][2] = fmaf(hv[3], p1[2], acc[1][nb][2]);
            acc[1][nb][3] = fmaf(hv[3], p1[3], acc[1][nb][3]);
        }
    }

#pragma unroll
    for (int blk = 0; blk < 2; blk++) {
        int jA = blk * 2, jB = blk * 2 + 1;
        int dA = g_dst[eb + er[jA]], dB = g_dst[eb + er[jB]];
#pragma unroll
        for (int nb = 0; nb < 8; nb++) {
            int o = nb * 8 + 2 * tig;
#define BSUM(j, oo) (xsf[j][0] * b2s[oo] + xsf[j][1] * b2s[64 + (oo)] \
                     + xsf[j][2] * b2s[128 + (oo)] + xsf[j][3] * b2s[192 + (oo)])
            atomicAdd(&g_sum1[(size_t)dA * HID + o],     acc[blk][nb][0] + BSUM(jA, o));
            atomicAdd(&g_sum1[(size_t)dA * HID + o + 1], acc[blk][nb][1] + BSUM(jA, o + 1));
            atomicAdd(&g_sum1[(size_t)dB * HID + o],     acc[blk][nb][2] + BSUM(jB, o));
            atomicAdd(&g_sum1[(size_t)dB * HID + o + 1], acc[blk][nb][3] + BSUM(jB, o + 1));
#undef BSUM
        }
    }
    if (tig == 0) {
#pragma unroll
        for (int j = 0; j < 4; j++) atomicAdd(&g_cnt[g_dst[eb + er[j]]], 1.f);
    }
}

// ---------------- kernel 2: layer-1 node update ----------------
__global__ void node_l1_kernel(const float* __restrict__ x,
                               const float* __restrict__ root1,
                               const float* __restrict__ bias1,
                               const float* __restrict__ lng,
                               const float* __restrict__ lnb) {
    int warp = (blockIdx.x * blockDim.x + threadIdx.x) >> 5;
    int lane = threadIdx.x & 31;
    int n = warp;
    if (n >= N_NODES) return;

    float inv = 1.f / fmaxf(g_cnt[n], 1.f);
    float4 xv = __ldg((const float4*)(x + (size_t)n * 4));
    float z0 = g_sum1[(size_t)n * HID + lane] * inv + __ldg(&bias1[lane])
             + xv.x * __ldg(&root1[lane])       + xv.y * __ldg(&root1[64 + lane])
             + xv.z * __ldg(&root1[128 + lane]) + xv.w * __ldg(&root1[192 + lane]);
    float z1 = g_sum1[(size_t)n * HID + 32 + lane] * inv + __ldg(&bias1[32 + lane])
             + xv.x * __ldg(&root1[32 + lane])  + xv.y * __ldg(&root1[96 + lane])
             + xv.z * __ldg(&root1[160 + lane]) + xv.w * __ldg(&root1[224 + lane]);
    z0 = fmaxf(z0, 0.f);
    z1 = fmaxf(z1, 0.f);

    float s = z0 + z1;
#pragma unroll
    for (int o = 16; o; o >>= 1) s += __shfl_xor_sync(0xffffffffu, s, o);
    float m = s * (1.f / 64.f);
    float d0 = z0 - m, d1 = z1 - m;
    float v = d0 * d0 + d1 * d1;
#pragma unroll
    for (int o = 16; o; o >>= 1) v += __shfl_xor_sync(0xffffffffu, v, o);
    v *= (1.f / 64.f);
    float is = rsqrtf(v + LN_EPS);
    g_h1[(size_t)n * HID + lane]      = d0 * is * __ldg(&lng[lane])      + __ldg(&lnb[lane]);
    g_h1[(size_t)n * HID + 32 + lane] = d1 * is * __ldg(&lng[32 + lane]) + __ldg(&lnb[32 + lane]);
}

// ---------------- kernel 3: layer-2 tensor-core kernel (v10: fragment-LDG) ------
__global__ void __launch_bounds__(128, 3) edge_l2_tc(
        const float* __restrict__ ea,
        const float* __restrict__ w1,   // e2_w1 [4,128]
        const float* __restrict__ b1) { // [128]
    __shared__ float w1s[512];
    __shared__ float b1s[128];

    int tid = threadIdx.x;
    int tile = blockIdx.x >> 1;
    int half = blockIdx.x & 1;
    int eb   = tile * 128;
    int k0   = half * 64;
    int kend = half ? 128 : 63;

#pragma unroll
    for (int q = 0; q < 4; q++) w1s[tid + q * 128] = __ldg(&w1[tid + q * 128]);
    b1s[tid] = __ldg(&b1[tid]);

    int lane = tid & 31, gID = lane >> 2, tig = lane & 3;
    int wb = (tid >> 5) * 32;
    int er[4] = {wb + gID, wb + 8 + gID, wb + 16 + gID, wb + 24 + gID};

    uint32_t A[2][4][4];
#pragma unroll
    for (int blk = 0; blk < 2; blk++) {
        const float* rA = g_h1 + (size_t)g_src[eb + er[blk * 2]] * HID;
        const float* rB = g_h1 + (size_t)g_src[eb + er[blk * 2 + 1]] * HID;
#pragma unroll
        for (int c = 0; c < 4; c++) {
            int i0 = c * 16 + 2 * tig;
            float2 x0 = __ldg((const float2*)(rA + i0));
            float2 x1 = __ldg((const float2*)(rB + i0));
            float2 x2 = __ldg((const float2*)(rA + i0 + 8));
            float2 x3 = __ldg((const float2*)(rB + i0 + 8));
            A[blk][c][0] = h2_pack(x0.x, x0.y);
            A[blk][c][1] = h2_pack(x1.x, x1.y);
            A[blk][c][2] = h2_pack(x2.x, x2.y);
            A[blk][c][3] = h2_pack(x3.x, x3.y);
        }
    }
    float4 aev[4];
#pragma unroll
    for (int j = 0; j < 4; j++)
        aev[j] = __ldg((const float4*)(ea + (size_t)(eb + er[j]) * 4));

    __syncthreads();   // only barrier: w1s/b1s ready

    float acc[2][8][4];
#pragma unroll
    for (int blk = 0; blk < 2; blk++)
#pragma unroll
        for (int nb = 0; nb < 8; nb++)
#pragma unroll
            for (int q = 0; q < 4; q++) acc[blk][nb][q] = 0.f;

    const uint4* Wbase = (const uint4*)g_Wf + (lane << 1);
    for (int k = k0; k <= kend; ++k) {
        float hv[4];
        if (k < 128) {
            float c0 = w1s[k], c1 = w1s[128 + k], c2 = w1s[256 + k], c3 = w1s[384 + k];
            float bb = b1s[k];
#pragma unroll
            for (int j = 0; j < 4; j++)
                hv[j] = fmaxf(fmaf(aev[j].w, c3, fmaf(aev[j].z, c2,
                              fmaf(aev[j].y, c1, fmaf(aev[j].x, c0, bb)))), 0.f);
        } else { hv[0] = hv[1] = hv[2] = hv[3] = 1.f; }

        const uint4* Wp = Wbase + (size_t)k * 512;
#pragma unroll
        for (int nb = 0; nb < 8; nb++) {
            uint4 v0 = __ldg(Wp + nb * 64);
            uint4 v1 = __ldg(Wp + nb * 64 + 1);
            float p0[4], p1[4];
            mma_f16_zc(p0, A[0][0][0], A[0][0][1], A[0][0][2], A[0][0][3], v0.x, v0.y);
            mma_f16(p0, A[0][1][0], A[0][1][1], A[0][1][2], A[0][1][3], v0.z, v0.w);
            mma_f16(p0, A[0][2][0], A[0][2][1], A[0][2][2], A[0][2][3], v1.x, v1.y);
            mma_f16(p0, A[0][3][0], A[0][3][1], A[0][3][2], A[0][3][3], v1.z, v1.w);
            mma_f16_zc(p1, A[1][0][0], A[1][0][1], A[1][0][2], A[1][0][3], v0.x, v0.y);
            mma_f16(p1, A[1][1][0], A[1][1][1], A[1][1][2], A[1][1][3], v0.z, v0.w);
            mma_f16(p1, A[1][2][0], A[1][2][1], A[1][2][2], A[1][2][3], v1.x, v1.y);
            mma_f16(p1, A[1][3][0], A[1][3][1], A[1][3][2], A[1][3][3], v1.z, v1.w);
            acc[0][nb][0] = fmaf(hv[0], p0[0], acc[0][nb][0]);
            acc[0][nb][1] = fmaf(hv[0], p0[1], acc[0][nb][1]);
            acc[0][nb][2] = fmaf(hv[1], p0[2], acc[0][nb][2]);
            acc[0][nb][3] = fmaf(hv[1], p0[3], acc[0][nb][3]);
            acc[1][nb][0] = fmaf(hv[2], p1[0], acc[1][nb][0]);
            acc[1][nb][1] = fmaf(hv[2], p1[1], acc[1][nb][1]);
            acc[1][nb][2] = fmaf(hv[3], p1[2], acc[1][nb][2]);
            acc[1][nb][3] = fmaf(hv[3], p1[3], acc[1][nb][3]);
        }
    }

#pragma unroll
    for (int blk = 0; blk < 2; blk++) {
        int dA = g_dst[eb + er[blk * 2]], dB = g_dst[eb + er[blk * 2 + 1]];
#pragma unroll
        for (int nb = 0; nb < 8; nb++) {
            int o = nb * 8 + 2 * tig;
            atomicAdd(&g_sum2[(size_t)dA * HID + o],     acc[blk][nb][0]);
            atomicAdd(&g_sum2[(size_t)dA * HID + o + 1], acc[blk][nb][1]);
            atomicAdd(&g_sum2[(size_t)dB * HID + o],     acc[blk][nb][2]);
            atomicAdd(&g_sum2[(size_t)dB * HID + o + 1], acc[blk][nb][3]);
        }
    }
}

// ---------------- kernel 4: layer-2 node update + LN + global mean pool ------------
__global__ void node_l2_kernel(const float* __restrict__ root2,
                               const float* __restrict__ bias2,
                               const float* __restrict__ lng,
                               const float* __restrict__ lnb,
                               float* __restrict__ out) {
    __shared__ float rt[4096];
    __shared__ float acc[64];
    int tid = threadIdx.x;
#pragma unroll
    for (int q = 0; q < 16; q++) rt[tid + q * 256] = __ldg(&root2[tid + q * 256]);
    if (tid < 64) acc[tid] = 0.f;
    __syncthreads();

    int warp = tid >> 5, lane = tid & 31;
    int n = blockIdx.x * 8 + warp;

    float a0 = g_h1[(size_t)n * HID + lane];
    float a1 = g_h1[(size_t)n * HID + 32 + lane];
    float inv = 1.f / fmaxf(g_cnt[n], 1.f);
    float z0 = g_sum2[(size_t)n * HID + lane] * inv + __ldg(&bias2[lane]);
    float z1 = g_sum2[(size_t)n * HID + 32 + lane] * inv + __ldg(&bias2[32 + lane]);

#pragma unroll 16
    for (int i = 0; i < 64; i++) {
        float hi = __shfl_sync(0xffffffffu, (i < 32) ? a0 : a1, i & 31);
        z0 = fmaf(hi, rt[i * 64 + lane], z0);
        z1 = fmaf(hi, rt[i * 64 + 32 + lane], z1);
    }
    z0 = fmaxf(z0, 0.f);
    z1 = fmaxf(z1, 0.f);

    float s = z0 + z1;
#pragma unroll
    for (int o = 16; o; o >>= 1) s += __shfl_xor_sync(0xffffffffu, s, o);
    float m = s * (1.f / 64.f);
    float d0 = z0 - m, d1 = z1 - m;
    float v = d0 * d0 + d1 * d1;
#pragma unroll
    for (int o = 16; o; o >>= 1) v += __shfl_xor_sync(0xffffffffu, v, o);
    v *= (1.f / 64.f);
    float is = rsqrtf(v + LN_EPS);
    float y0 = d0 * is * __ldg(&lng[lane])      + __ldg(&lnb[lane]);
    float y1 = d1 * is * __ldg(&lng[32 + lane]) + __ldg(&lnb[32 + lane]);

    atomicAdd(&acc[lane],      y0 * (1.f / (float)N_NODES));
    atomicAdd(&acc[32 + lane], y1 * (1.f / (float)N_NODES));
    __syncthreads();
    if (tid < 64) atomicAdd(&out[tid], acc[tid]);
}

// ---------------- launch: robust input-order resolution ----------------
static const int EXP_SIZE[20] = {
    131072, 262144, 131072, 32768, 256, 64, 16384, 256, 256, 64, 64, 64,
    512, 128, 524288, 4096, 4096, 64, 64, 64};

static const int PERM_DICT[20]  = {0,1,2,3,4,5,6,7,8,9,10,11,12,13,14,15,16,17,18,19};
static const int PERM_SIG[20]   = {0,1,18,19,2,3,4,5,6,7,8,9,10,11,12,13,14,15,16,17};
static const int PERM_ALPHA[20] = {19,11,12,0,5,3,6,4,17,1,14,13,9,7,10,8,18,2,16,15};

extern "C" void kernel_launch(void* const* d_in, const int* in_sizes, int n_in,
                              void* d_out, int out_size) {
    const int* perm = PERM_DICT;
    const int* cands[3] = {PERM_DICT, PERM_SIG, PERM_ALPHA};
    for (int p = 0; p < 3; p++) {
        bool ok = (n_in >= 20);
        for (int c = 0; ok && c < 20; c++)
            if (in_sizes[cands[p][c]] != EXP_SIZE[c]) ok = false;
        if (ok) { perm = cands[p]; break; }
    }

    const float* x    = (const float*)d_in[perm[0]];
    const float* ea   = (const float*)d_in[perm[1]];
    const void*  eidx = d_in[perm[2]];
    const float* e1_w1 = (const float*)d_in[perm[4]];
    const float* e1_b1 = (const float*)d_in[perm[5]];
    const float* e1_w2 = (const float*)d_in[perm[6]];
    const float* e1_b2 = (const float*)d_in[perm[7]];
    const float* root1 = (const float*)d_in[perm[8]];
    const float* bias1 = (const float*)d_in[perm[9]];
    const float* ln1_g = (const float*)d_in[perm[10]];
    const float* ln1_b = (const float*)d_in[perm[11]];
    const float* e2_w1 = (const float*)d_in[perm[12]];
    const float* e2_b1 = (const float*)d_in[perm[13]];
    const float* e2_w2 = (const float*)d_in[perm[14]];
    const float* e2_b2 = (const float*)d_in[perm[15]];
    const float* root2 = (const float*)d_in[perm[16]];
    const float* bias2 = (const float*)d_in[perm[17]];
    const float* ln2_g = (const float*)d_in[perm[18]];
    const float* ln2_b = (const float*)d_in[perm[19]];
    float* out = (float*)d_out;

    fused_prep<<<ZB + PB + SB_BLK + SB1_BLK, 256>>>(eidx, e2_w2, e2_b2, e1_w2, out);
    edge_l1_tc<<<N_EDGES / 128, 128>>>(x, ea, e1_w1, e1_b1, e1_b2);
    node_l1_kernel<<<N_NODES / 8, 256>>>(x, root1, bias1, ln1_g, ln1_b);
    edge_l2_tc<<<2 * (N_EDGES / 128), 128>>>(ea, e2_w1, e2_b1);
    node_l2_kernel<<<N_NODES / 8, 256>>>(root2, bias2, ln2_g, ln2_b, out);
}

// round 15
// speedup vs baseline: 1.1330x; 1.1330x over previous
#include <cuda_runtime.h>
#include <cuda_bf16.h>
#include <cuda_fp16.h>
#include <cstdint>

#define N_NODES 32768
#define N_EDGES 65536
#define HID 64
#define LN_EPS 1e-5f

// ---------------- scratch (static device globals; no allocation) ----------------
__device__ float g_sum1[N_NODES * HID];
__device__ float g_sum2[N_NODES * HID];
__device__ float g_cnt[N_NODES];
__device__ float g_h1[N_NODES * HID];
__device__ int   g_src[N_EDGES];
__device__ int   g_dst[N_EDGES];
// layer-2 weights fp16 transposed: [k=0..128][o][i] packed half2 (i even/odd):
// g_Wh[k*2048 + o*32 + i/2]; k==128 -> bias b2 (layer-2).
__device__ uint32_t g_Wh[129 * 2048];
// layer-1 w2 fp16: chunk i (=input channel): g_Wh1[i*2048 + o*32 + k/2]
__device__ uint32_t g_Wh1[4 * 2048];

__device__ __forceinline__ int clamp_node(long long v) {
    return v < 0 ? 0 : (v >= N_NODES ? N_NODES - 1 : (int)v);
}

__device__ __forceinline__ uint32_t h2_pack(float v0, float v1) {
    __half2 h = __float22half2_rn(make_float2(v0, v1));
    return *reinterpret_cast<uint32_t*>(&h);
}
__device__ __forceinline__ void mma_f16(float* c,
        uint32_t a0, uint32_t a1, uint32_t a2, uint32_t a3,
        uint32_t b0, uint32_t b1) {
    asm volatile(
        "mma.sync.aligned.m16n8k16.row.col.f32.f16.f16.f32 "
        "{%0,%1,%2,%3}, {%4,%5,%6,%7}, {%8,%9}, {%0,%1,%2,%3};\n"
        : "+f"(c[0]), "+f"(c[1]), "+f"(c[2]), "+f"(c[3])
        : "r"(a0), "r"(a1), "r"(a2), "r"(a3), "r"(b0), "r"(b1));
}
__device__ __forceinline__ void mma_f16_zc(float* c,
        uint32_t a0, uint32_t a1, uint32_t a2, uint32_t a3,
        uint32_t b0, uint32_t b1) {
    asm volatile(
        "mma.sync.aligned.m16n8k16.row.col.f32.f16.f16.f32 "
        "{%0,%1,%2,%3}, {%4,%5,%6,%7}, {%8,%9}, {%10,%11,%12,%13};\n"
        : "=f"(c[0]), "=f"(c[1]), "=f"(c[2]), "=f"(c[3])
        : "r"(a0), "r"(a1), "r"(a2), "r"(a3), "r"(b0), "r"(b1),
          "f"(0.f), "f"(0.f), "f"(0.f), "f"(0.f));
}
__device__ __forceinline__ void ldsm_x4(uint32_t& r0, uint32_t& r1,
                                        uint32_t& r2, uint32_t& r3, uint32_t saddr) {
    asm volatile("ldmatrix.sync.aligned.m8n8.x4.shared.b16 {%0,%1,%2,%3}, [%4];\n"
        : "=r"(r0), "=r"(r1), "=r"(r2), "=r"(r3) : "r"(saddr));
}
__device__ __forceinline__ uint32_t smem_u32(const void* p) {
    uint32_t a;
    asm("{ .reg .u64 t; cvta.to.shared.u64 t, %1; cvt.u32.u64 %0, t; }" : "=r"(a) : "l"(p));
    return a;
}
__device__ __forceinline__ void cp_async16(uint32_t dst_s, const void* src_g) {
    asm volatile("cp.async.cg.shared.global [%0], [%1], 16;"
                 :: "r"(dst_s), "l"(src_g) : "memory");
}

// ---------------- kernel 0 (fused): zero + edge prep + w2(l2) + w2(l1) pack ----
#define ZB 8192
#define PB 256
#define SB_BLK 129
#define SB1_BLK 4
__global__ void fused_prep(const void* __restrict__ eidx_raw,
                           const float* __restrict__ w2,    // e2_w2 [128,4096]
                           const float* __restrict__ b2,    // [4096]
                           const float* __restrict__ w2l1,  // e1_w2 [64,256]
                           float* __restrict__ out) {
    int b = blockIdx.x, tid = threadIdx.x;
    if (b < ZB) {
        int idx = b * 256 + tid;
        g_sum1[idx] = 0.f; g_sum2[idx] = 0.f;
        if (idx < N_NODES) g_cnt[idx] = 0.f;
        if (idx < HID) out[idx] = 0.f;
    } else if (b < ZB + PB) {
        const long long* p64 = (const long long*)eidx_raw;
        const int*       p32 = (const int*)eidx_raw;
        bool is64 = true;
#pragma unroll
        for (int i = 0; i < 8; i++) {
            long long v = p64[i];
            if (v < 0 || v >= N_NODES) { is64 = false; break; }
        }
        int e = (b - ZB) * 256 + tid;
        long long s, d;
        if (is64) { s = p64[e]; d = p64[N_EDGES + e]; }
        else      { s = p32[e]; d = p32[N_EDGES + e]; }
        g_src[e] = clamp_node(s);
        g_dst[e] = clamp_node(d);
    } else if (b < ZB + PB + SB_BLK) {
        int k = b - ZB - PB;
        int o = tid & 63;
        int q = tid >> 6;
        const float* src = (k < 128) ? (w2 + (size_t)k * 4096) : b2;
        size_t base = (size_t)k * 2048 + o * 32;
#pragma unroll
        for (int jj = 0; jj < 8; jj++) {
            int j = q * 8 + jj;
            float v0 = __ldg(&src[(2 * j) * 64 + o]);
            float v1 = __ldg(&src[(2 * j + 1) * 64 + o]);
            g_Wh[base + j] = h2_pack(v0, v1);
        }
    } else {
        int i = b - ZB - PB - SB_BLK;     // input-channel chunk 0..3
        int o = tid & 63;
        int q = tid >> 6;
        size_t base = (size_t)i * 2048 + o * 32;
#pragma unroll
        for (int jj = 0; jj < 8; jj++) {
            int j = q * 8 + jj;           // k-pair index (hidden dim)
            float v0 = __ldg(&w2l1[(2 * j) * 256 + i * 64 + o]);
            float v1 = __ldg(&w2l1[(2 * j + 1) * 256 + i * 64 + o]);
            g_Wh1[base + j] = h2_pack(v0, v1);
        }
    }
}

// ---------------- kernel 1: layer-1 edge pipeline on tensor cores (R13 version) -
__global__ void __launch_bounds__(128, 3) edge_l1_tc(
        const float* __restrict__ x,
        const float* __restrict__ ea,
        const float* __restrict__ w1,   // e1_w1 [4,64]
        const float* __restrict__ b1,   // [64]
        const float* __restrict__ b2) { // [256]
    __shared__ uint32_t SB1[4][2048];   // 32 KB (4 chunks x 8 KB)
    __shared__ float w1s[256];
    __shared__ float b1s[64];
    __shared__ float b2s[256];
    __shared__ int   dst_s[128];

    int tid = threadIdx.x;
    int eb  = blockIdx.x * 128;
    uint32_t sbase = smem_u32(&SB1[0][0]);

#pragma unroll
    for (int i = 0; i < 4; i++) {
        const uint32_t* gW = g_Wh1 + (size_t)i * 2048;
#pragma unroll
        for (int q = 0; q < 4; q++) {
            int u = tid * 4 + q;
            int o = u >> 3, ch = u & 7;
            cp_async16(sbase + (uint32_t)i * 8192
                       + (uint32_t)(o * 32 + ((ch ^ (o & 7)) << 2)) * 4,
                       gW + u * 4);
        }
    }
    asm volatile("cp.async.commit_group;" ::: "memory");

    w1s[tid] = __ldg(&w1[tid]);
    w1s[128 + tid] = __ldg(&w1[128 + tid]);
    if (tid < 64) b1s[tid] = __ldg(&b1[tid]);
    b2s[tid] = __ldg(&b2[tid]);
    b2s[128 + tid] = __ldg(&b2[128 + tid]);
    dst_s[tid] = g_dst[eb + tid];

    int lane = tid & 31, gID = lane >> 2, tig = lane & 3;
    int wb = (tid >> 5) * 32;
    int er[4] = {wb + gID, wb + 8 + gID, wb + 16 + gID, wb + 24 + gID};

    float4 aev[4];
    float  xsf[4][4];
#pragma unroll
    for (int j = 0; j < 4; j++) {
        aev[j] = __ldg((const float4*)(ea + (size_t)(eb + er[j]) * 4));
        float4 xv = __ldg((const float4*)(x + (size_t)g_src[eb + er[j]] * 4));
        xsf[j][0] = xv.x; xsf[j][1] = xv.y; xsf[j][2] = xv.z; xsf[j][3] = xv.w;
    }

    asm volatile("cp.async.wait_group 0;" ::: "memory");
    __syncthreads();

    uint32_t A1[2][4][4];
#pragma unroll
    for (int blk = 0; blk < 2; blk++) {
        float4 eA = aev[blk * 2], eB = aev[blk * 2 + 1];
#pragma unroll
        for (int c = 0; c < 4; c++) {
            int k0 = c * 16 + 2 * tig;
            float hA0, hA1, hA2, hA3, hB0, hB1, hB2, hB3;
#define H1F(a, k) fmaxf(b1s[k] + (a).x * w1s[k] + (a).y * w1s[64 + (k)] \
                        + (a).z * w1s[128 + (k)] + (a).w * w1s[192 + (k)], 0.f)
            hA0 = H1F(eA, k0);     hA1 = H1F(eA, k0 + 1);
            hB0 = H1F(eB, k0);     hB1 = H1F(eB, k0 + 1);
            hA2 = H1F(eA, k0 + 8); hA3 = H1F(eA, k0 + 9);
            hB2 = H1F(eB, k0 + 8); hB3 = H1F(eB, k0 + 9);
#undef H1F
            A1[blk][c][0] = h2_pack(hA0, hA1);
            A1[blk][c][1] = h2_pack(hB0, hB1);
            A1[blk][c][2] = h2_pack(hA2, hA3);
            A1[blk][c][3] = h2_pack(hB2, hB3);
        }
    }

    int lm_m = lane >> 3, lm_r = lane & 7;

    float acc[2][8][4];
#pragma unroll
    for (int blk = 0; blk < 2; blk++)
#pragma unroll
        for (int nt = 0; nt < 8; nt++)
#pragma unroll
            for (int q = 0; q < 4; q++) acc[blk][nt][q] = 0.f;

#pragma unroll
    for (int i = 0; i < 4; i++) {
        uint32_t bh = sbase + (uint32_t)i * 8192;
        float hv[4] = {xsf[0][i], xsf[1][i], xsf[2][i], xsf[3][i]};

#pragma unroll
        for (int ntp = 0; ntp < 4; ntp++) {
            float p0e[4], p0o[4], p1e[4], p1o[4];
#pragma unroll
            for (int c = 0; c < 4; c++) {
                int o  = (ntp * 2 + (lm_m >> 1)) * 8 + lm_r;
                int ch = c * 2 + (lm_m & 1);
                uint32_t off = (uint32_t)(o * 32 + ((ch ^ (o & 7)) << 2)) << 2;
                uint32_t r0, r1, r2, r3;
                ldsm_x4(r0, r1, r2, r3, bh + off);
                if (c == 0) {
                    mma_f16_zc(p0e, A1[0][0][0], A1[0][0][1], A1[0][0][2], A1[0][0][3], r0, r1);
                    mma_f16_zc(p0o, A1[0][0][0], A1[0][0][1], A1[0][0][2], A1[0][0][3], r2, r3);
                    mma_f16_zc(p1e, A1[1][0][0], A1[1][0][1], A1[1][0][2], A1[1][0][3], r0, r1);
                    mma_f16_zc(p1o, A1[1][0][0], A1[1][0][1], A1[1][0][2], A1[1][0][3], r2, r3);
                } else {
                    mma_f16(p0e, A1[0][c][0], A1[0][c][1], A1[0][c][2], A1[0][c][3], r0, r1);
                    mma_f16(p0o, A1[0][c][0], A1[0][c][1], A1[0][c][2], A1[0][c][3], r2, r3);
                    mma_f16(p1e, A1[1][c][0], A1[1][c][1], A1[1][c][2], A1[1][c][3], r0, r1);
                    mma_f16(p1o, A1[1][c][0], A1[1][c][1], A1[1][c][2], A1[1][c][3], r2, r3);
                }
            }
            int nt = ntp * 2;
            acc[0][nt][0]     = fmaf(hv[0], p0e[0], acc[0][nt][0]);
            acc[0][nt][1]     = fmaf(hv[0], p0e[1], acc[0][nt][1]);
            acc[0][nt][2]     = fmaf(hv[1], p0e[2], acc[0][nt][2]);
            acc[0][nt][3]     = fmaf(hv[1], p0e[3], acc[0][nt][3]);
            acc[0][nt + 1][0] = fmaf(hv[0], p0o[0], acc[0][nt + 1][0]);
            acc[0][nt + 1][1] = fmaf(hv[0], p0o[1], acc[0][nt + 1][1]);
            acc[0][nt + 1][2] = fmaf(hv[1], p0o[2], acc[0][nt + 1][2]);
            acc[0][nt + 1][3] = fmaf(hv[1], p0o[3], acc[0][nt + 1][3]);
            acc[1][nt][0]     = fmaf(hv[2], p1e[0], acc[1][nt][0]);
            acc[1][nt][1]     = fmaf(hv[2], p1e[1], acc[1][nt][1]);
            acc[1][nt][2]     = fmaf(hv[3], p1e[2], acc[1][nt][2]);
            acc[1][nt][3]     = fmaf(hv[3], p1e[3], acc[1][nt][3]);
            acc[1][nt + 1][0] = fmaf(hv[2], p1o[0], acc[1][nt + 1][0]);
            acc[1][nt + 1][1] = fmaf(hv[2], p1o[1], acc[1][nt + 1][1]);
            acc[1][nt + 1][2] = fmaf(hv[3], p1o[2], acc[1][nt + 1][2]);
            acc[1][nt + 1][3] = fmaf(hv[3], p1o[3], acc[1][nt + 1][3]);
        }
    }

#pragma unroll
    for (int blk = 0; blk < 2; blk++) {
        int jA = blk * 2, jB = blk * 2 + 1;
        int dA = dst_s[er[jA]], dB = dst_s[er[jB]];
#pragma unroll
        for (int nt = 0; nt < 8; nt++) {
            int o = nt * 8 + 2 * tig;
#define BSUM(j, oo) (xsf[j][0] * b2s[oo] + xsf[j][1] * b2s[64 + (oo)] \
                     + xsf[j][2] * b2s[128 + (oo)] + xsf[j][3] * b2s[192 + (oo)])
            atomicAdd(&g_sum1[(size_t)dA * HID + o],     acc[blk][nt][0] + BSUM(jA, o));
            atomicAdd(&g_sum1[(size_t)dA * HID + o + 1], acc[blk][nt][1] + BSUM(jA, o + 1));
            atomicAdd(&g_sum1[(size_t)dB * HID + o],     acc[blk][nt][2] + BSUM(jB, o));
            atomicAdd(&g_sum1[(size_t)dB * HID + o + 1], acc[blk][nt][3] + BSUM(jB, o + 1));
#undef BSUM
        }
    }
    if (tig == 0) {
#pragma unroll
        for (int j = 0; j < 4; j++) atomicAdd(&g_cnt[dst_s[er[j]]], 1.f);
    }
}

// ---------------- kernel 2: layer-1 node update ----------------
__global__ void node_l1_kernel(const float* __restrict__ x,
                               const float* __restrict__ root1,
                               const float* __restrict__ bias1,
                               const float* __restrict__ lng,
                               const float* __restrict__ lnb) {
    int warp = (blockIdx.x * blockDim.x + threadIdx.x) >> 5;
    int lane = threadIdx.x & 31;
    int n = warp;
    if (n >= N_NODES) return;

    float inv = 1.f / fmaxf(g_cnt[n], 1.f);
    float4 xv = __ldg((const float4*)(x + (size_t)n * 4));
    float z0 = g_sum1[(size_t)n * HID + lane] * inv + __ldg(&bias1[lane])
             + xv.x * __ldg(&root1[lane])       + xv.y * __ldg(&root1[64 + lane])
             + xv.z * __ldg(&root1[128 + lane]) + xv.w * __ldg(&root1[192 + lane]);
    float z1 = g_sum1[(size_t)n * HID + 32 + lane] * inv + __ldg(&bias1[32 + lane])
             + xv.x * __ldg(&root1[32 + lane])  + xv.y * __ldg(&root1[96 + lane])
             + xv.z * __ldg(&root1[160 + lane]) + xv.w * __ldg(&root1[224 + lane]);
    z0 = fmaxf(z0, 0.f);
    z1 = fmaxf(z1, 0.f);

    float s = z0 + z1;
#pragma unroll
    for (int o = 16; o; o >>= 1) s += __shfl_xor_sync(0xffffffffu, s, o);
    float m = s * (1.f / 64.f);
    float d0 = z0 - m, d1 = z1 - m;
    float v = d0 * d0 + d1 * d1;
#pragma unroll
    for (int o = 16; o; o >>= 1) v += __shfl_xor_sync(0xffffffffu, v, o);
    v *= (1.f / 64.f);
    float is = rsqrtf(v + LN_EPS);
    g_h1[(size_t)n * HID + lane]      = d0 * is * __ldg(&lng[lane])      + __ldg(&lnb[lane]);
    g_h1[(size_t)n * HID + 32 + lane] = d1 * is * __ldg(&lng[32 + lane]) + __ldg(&lnb[32 + lane]);
}

// ---------------- kernel 3: layer-2 tensor-core kernel (v11: 8-slot ring) -------
// R13 v9 structure (k-split x2, smem+ldsm, cp.async) with an 8-slot 64KB dynamic
// smem ring: one __syncthreads per 4 k-tiles instead of per 2.
extern __shared__ uint32_t SBUF[];   // 8 slots x 2048 u32 = 64 KB
__global__ void __launch_bounds__(128, 3) edge_l2_tc(
        const float* __restrict__ ea,
        const float* __restrict__ w1,   // e2_w1 [4,128]
        const float* __restrict__ b1) { // [128]
    __shared__ float w1s[512];
    __shared__ float b1s[128];
    __shared__ int   dst_s[128];

    int tid = threadIdx.x;
    int tile = blockIdx.x >> 1;
    int half = blockIdx.x & 1;
    int eb   = tile * 128;
    int k0   = half * 64;
    int kend = half ? 128 : 63;

#pragma unroll
    for (int q = 0; q < 4; q++) w1s[tid + q * 128] = __ldg(&w1[tid + q * 128]);
    b1s[tid] = __ldg(&b1[tid]);
    dst_s[tid] = g_dst[eb + tid];

    int lane = tid & 31, gID = lane >> 2, tig = lane & 3;
    int wb = (tid >> 5) * 32;
    int er[4] = {wb + gID, wb + 8 + gID, wb + 16 + gID, wb + 24 + gID};

    uint32_t sbase = smem_u32(SBUF);

    uint32_t st_off[4];
#pragma unroll
    for (int q = 0; q < 4; q++) {
        int u = tid * 4 + q;
        int o = u >> 3, ch = u & 7;
        st_off[q] = (uint32_t)(o * 32 + ((ch ^ (o & 7)) << 2)) * 4;
    }

    // prologue: stage tiles k0..k0+3 into slots 0..3
#pragma unroll
    for (int t = 0; t < 4; t++) {
        int kn = k0 + t;
        if (kn <= kend) {
            const uint32_t* gW = g_Wh + (size_t)kn * 2048;
            uint32_t dbase = sbase + (uint32_t)t * 8192;
#pragma unroll
            for (int q = 0; q < 4; q++)
                cp_async16(dbase + st_off[q], gW + (tid * 4 + q) * 4);
        }
    }
    asm volatile("cp.async.commit_group;" ::: "memory");

    // gather H1[src] -> registers as single fp16 (overlaps cp.async)
    uint32_t A[2][4][4];
#pragma unroll
    for (int blk = 0; blk < 2; blk++) {
        const float* rA = g_h1 + (size_t)g_src[eb + er[blk * 2]] * HID;
        const float* rB = g_h1 + (size_t)g_src[eb + er[blk * 2 + 1]] * HID;
#pragma unroll
        for (int c = 0; c < 4; c++) {
            int i0 = c * 16 + 2 * tig;
            float2 x0 = __ldg((const float2*)(rA + i0));
            float2 x1 = __ldg((const float2*)(rB + i0));
            float2 x2 = __ldg((const float2*)(rA + i0 + 8));
            float2 x3 = __ldg((const float2*)(rB + i0 + 8));
            A[blk][c][0] = h2_pack(x0.x, x0.y);
            A[blk][c][1] = h2_pack(x1.x, x1.y);
            A[blk][c][2] = h2_pack(x2.x, x2.y);
            A[blk][c][3] = h2_pack(x3.x, x3.y);
        }
    }
    float4 aev[4];
#pragma unroll
    for (int j = 0; j < 4; j++)
        aev[j] = __ldg((const float4*)(ea + (size_t)(eb + er[j]) * 4));

    asm volatile("cp.async.wait_group 0;" ::: "memory");
    __syncthreads();

    int lm_m = lane >> 3, lm_r = lane & 7;

    float acc[2][8][4];
#pragma unroll
    for (int blk = 0; blk < 2; blk++)
#pragma unroll
        for (int nt = 0; nt < 8; nt++)
#pragma unroll
            for (int q = 0; q < 4; q++) acc[blk][nt][q] = 0.f;

    for (int kk = k0; kk <= kend; kk += 4) {
        // stage tiles kk+4..kk+7 into their ring slots
#pragma unroll
        for (int t = 0; t < 4; t++) {
            int kn = kk + 4 + t;
            if (kn <= kend) {
                const uint32_t* gW = g_Wh + (size_t)kn * 2048;
                uint32_t dbase = sbase + (uint32_t)((kn - k0) & 7) * 8192;
#pragma unroll
                for (int q = 0; q < 4; q++)
                    cp_async16(dbase + st_off[q], gW + (tid * 4 + q) * 4);
            }
        }
        asm volatile("cp.async.commit_group;" ::: "memory");

        // compute tiles kk..kk+3
#pragma unroll
        for (int t = 0; t < 4; t++) {
            int k = kk + t;
            if (k > kend) break;
            uint32_t bh = sbase + (uint32_t)((k - k0) & 7) * 8192;

            float hv[4];
            if (k < 128) {
                float c0 = w1s[k], c1 = w1s[128 + k], c2 = w1s[256 + k], c3 = w1s[384 + k];
                float bb = b1s[k];
#pragma unroll
                for (int j = 0; j < 4; j++)
                    hv[j] = fmaxf(fmaf(aev[j].w, c3, fmaf(aev[j].z, c2,
                                  fmaf(aev[j].y, c1, fmaf(aev[j].x, c0, bb)))), 0.f);
            } else { hv[0] = hv[1] = hv[2] = hv[3] = 1.f; }

#pragma unroll
            for (int ntp = 0; ntp < 4; ntp++) {
                float p0e[4], p0o[4], p1e[4], p1o[4];
#pragma unroll
                for (int c = 0; c < 4; c++) {
                    int o  = (ntp * 2 + (lm_m >> 1)) * 8 + lm_r;
                    int ch = c * 2 + (lm_m & 1);
                    uint32_t off = (uint32_t)(o * 32 + ((ch ^ (o & 7)) << 2)) << 2;
                    uint32_t r0, r1, r2, r3;
                    ldsm_x4(r0, r1, r2, r3, bh + off);
                    if (c == 0) {
                        mma_f16_zc(p0e, A[0][0][0], A[0][0][1], A[0][0][2], A[0][0][3], r0, r1);
                        mma_f16_zc(p0o, A[0][0][0], A[0][0][1], A[0][0][2], A[0][0][3], r2, r3);
                        mma_f16_zc(p1e, A[1][0][0], A[1][0][1], A[1][0][2], A[1][0][3], r0, r1);
                        mma_f16_zc(p1o, A[1][0][0], A[1][0][1], A[1][0][2], A[1][0][3], r2, r3);
                    } else {
                        mma_f16(p0e, A[0][c][0], A[0][c][1], A[0][c][2], A[0][c][3], r0, r1);
                        mma_f16(p0o, A[0][c][0], A[0][c][1], A[0][c][2], A[0][c][3], r2, r3);
                        mma_f16(p1e, A[1][c][0], A[1][c][1], A[1][c][2], A[1][c][3], r0, r1);
                        mma_f16(p1o, A[1][c][0], A[1][c][1], A[1][c][2], A[1][c][3], r2, r3);
                    }
                }
                int nt = ntp * 2;
                acc[0][nt][0]     = fmaf(hv[0], p0e[0], acc[0][nt][0]);
                acc[0][nt][1]     = fmaf(hv[0], p0e[1], acc[0][nt][1]);
                acc[0][nt][2]     = fmaf(hv[1], p0e[2], acc[0][nt][2]);
                acc[0][nt][3]     = fmaf(hv[1], p0e[3], acc[0][nt][3]);
                acc[0][nt + 1][0] = fmaf(hv[0], p0o[0], acc[0][nt + 1][0]);
                acc[0][nt + 1][1] = fmaf(hv[0], p0o[1], acc[0][nt + 1][1]);
                acc[0][nt + 1][2] = fmaf(hv[1], p0o[2], acc[0][nt + 1][2]);
                acc[0][nt + 1][3] = fmaf(hv[1], p0o[3], acc[0][nt + 1][3]);
                acc[1][nt][0]     = fmaf(hv[2], p1e[0], acc[1][nt][0]);
                acc[1][nt][1]     = fmaf(hv[2], p1e[1], acc[1][nt][1]);
                acc[1][nt][2]     = fmaf(hv[3], p1e[2], acc[1][nt][2]);
                acc[1][nt][3]     = fmaf(hv[3], p1e[3], acc[1][nt][3]);
                acc[1][nt + 1][0] = fmaf(hv[2], p1o[0], acc[1][nt + 1][0]);
                acc[1][nt + 1][1] = fmaf(hv[2], p1o[1], acc[1][nt + 1][1]);
                acc[1][nt + 1][2] = fmaf(hv[3], p1o[2], acc[1][nt + 1][2]);
                acc[1][nt + 1][3] = fmaf(hv[3], p1o[3], acc[1][nt + 1][3]);
            }
        }

        asm volatile("cp.async.wait_group 0;" ::: "memory");
        __syncthreads();
    }

    // epilogue: scatter partial messages
#pragma unroll
    for (int blk = 0; blk < 2; blk++) {
        int dA = dst_s[er[blk * 2]], dB = dst_s[er[blk * 2 + 1]];
#pragma unroll
        for (int nt = 0; nt < 8; nt++) {
            int o = nt * 8 + 2 * tig;
            atomicAdd(&g_sum2[(size_t)dA * HID + o],     acc[blk][nt][0]);
            atomicAdd(&g_sum2[(size_t)dA * HID + o + 1], acc[blk][nt][1]);
            atomicAdd(&g_sum2[(size_t)dB * HID + o],     acc[blk][nt][2]);
            atomicAdd(&g_sum2[(size_t)dB * HID + o + 1], acc[blk][nt][3]);
        }
    }
}

// ---------------- kernel 4: layer-2 node update + LN + global mean pool ------------
__global__ void node_l2_kernel(const float* __restrict__ root2,
                               const float* __restrict__ bias2,
                               const float* __restrict__ lng,
                               const float* __restrict__ lnb,
                               float* __restrict__ out) {
    __shared__ float rt[4096];
    __shared__ float acc[64];
    int tid = threadIdx.x;
#pragma unroll
    for (int q = 0; q < 16; q++) rt[tid + q * 256] = __ldg(&root2[tid + q * 256]);
    if (tid < 64) acc[tid] = 0.f;
    __syncthreads();

    int warp = tid >> 5, lane = tid & 31;
    int n = blockIdx.x * 8 + warp;

    float a0 = g_h1[(size_t)n * HID + lane];
    float a1 = g_h1[(size_t)n * HID + 32 + lane];
    float inv = 1.f / fmaxf(g_cnt[n], 1.f);
    float z0 = g_sum2[(size_t)n * HID + lane] * inv + __ldg(&bias2[lane]);
    float z1 = g_sum2[(size_t)n * HID + 32 + lane] * inv + __ldg(&bias2[32 + lane]);

#pragma unroll 16
    for (int i = 0; i < 64; i++) {
        float hi = __shfl_sync(0xffffffffu, (i < 32) ? a0 : a1, i & 31);
        z0 = fmaf(hi, rt[i * 64 + lane], z0);
        z1 = fmaf(hi, rt[i * 64 + 32 + lane], z1);
    }
    z0 = fmaxf(z0, 0.f);
    z1 = fmaxf(z1, 0.f);

    float s = z0 + z1;
#pragma unroll
    for (int o = 16; o; o >>= 1) s += __shfl_xor_sync(0xffffffffu, s, o);
    float m = s * (1.f / 64.f);
    float d0 = z0 - m, d1 = z1 - m;
    float v = d0 * d0 + d1 * d1;
#pragma unroll
    for (int o = 16; o; o >>= 1) v += __shfl_xor_sync(0xffffffffu, v, o);
    v *= (1.f / 64.f);
    float is = rsqrtf(v + LN_EPS);
    float y0 = d0 * is * __ldg(&lng[lane])      + __ldg(&lnb[lane]);
    float y1 = d1 * is * __ldg(&lng[32 + lane]) + __ldg(&lnb[32 + lane]);

    atomicAdd(&acc[lane],      y0 * (1.f / (float)N_NODES));
    atomicAdd(&acc[32 + lane], y1 * (1.f / (float)N_NODES));
    __syncthreads();
    if (tid < 64) atomicAdd(&out[tid], acc[tid]);
}

// ---------------- launch: robust input-order resolution ----------------
static const int EXP_SIZE[20] = {
    131072, 262144, 131072, 32768, 256, 64, 16384, 256, 256, 64, 64, 64,
    512, 128, 524288, 4096, 4096, 64, 64, 64};

static const int PERM_DICT[20]  = {0,1,2,3,4,5,6,7,8,9,10,11,12,13,14,15,16,17,18,19};
static const int PERM_SIG[20]   = {0,1,18,19,2,3,4,5,6,7,8,9,10,11,12,13,14,15,16,17};
static const int PERM_ALPHA[20] = {19,11,12,0,5,3,6,4,17,1,14,13,9,7,10,8,18,2,16,15};

extern "C" void kernel_launch(void* const* d_in, const int* in_sizes, int n_in,
                              void* d_out, int out_size) {
    const int* perm = PERM_DICT;
    const int* cands[3] = {PERM_DICT, PERM_SIG, PERM_ALPHA};
    for (int p = 0; p < 3; p++) {
        bool ok = (n_in >= 20);
        for (int c = 0; ok && c < 20; c++)
            if (in_sizes[cands[p][c]] != EXP_SIZE[c]) ok = false;
        if (ok) { perm = cands[p]; break; }
    }

    const float* x    = (const float*)d_in[perm[0]];
    const float* ea   = (const float*)d_in[perm[1]];
    const void*  eidx = d_in[perm[2]];
    const float* e1_w1 = (const float*)d_in[perm[4]];
    const float* e1_b1 = (const float*)d_in[perm[5]];
    const float* e1_w2 = (const float*)d_in[perm[6]];
    const float* e1_b2 = (const float*)d_in[perm[7]];
    const float* root1 = (const float*)d_in[perm[8]];
    const float* bias1 = (const float*)d_in[perm[9]];
    const float* ln1_g = (const float*)d_in[perm[10]];
    const float* ln1_b = (const float*)d_in[perm[11]];
    const float* e2_w1 = (const float*)d_in[perm[12]];
    const float* e2_b1 = (const float*)d_in[perm[13]];
    const float* e2_w2 = (const float*)d_in[perm[14]];
    const float* e2_b2 = (const float*)d_in[perm[15]];
    const float* root2 = (const float*)d_in[perm[16]];
    const float* bias2 = (const float*)d_in[perm[17]];
    const float* ln2_g = (const float*)d_in[perm[18]];
    const float* ln2_b = (const float*)d_in[perm[19]];
    float* out = (float*)d_out;

    static int smem_set = 0;
    if (!smem_set) {
        cudaFuncSetAttribute(edge_l2_tc, cudaFuncAttributeMaxDynamicSharedMemorySize, 65536);
        smem_set = 1;
    }

    fused_prep<<<ZB + PB + SB_BLK + SB1_BLK, 256>>>(eidx, e2_w2, e2_b2, e1_w2, out);
    edge_l1_tc<<<N_EDGES / 128, 128>>>(x, ea, e1_w1, e1_b1, e1_b2);
    node_l1_kernel<<<N_NODES / 8, 256>>>(x, root1, bias1, ln1_g, ln1_b);
    edge_l2_tc<<<2 * (N_EDGES / 128), 128, 65536>>>(ea, e2_w1, e2_b1);
    node_l2_kernel<<<N_NODES / 8, 256>>>(root2, bias2, ln2_g, ln2_b, out);
}

// round 16
// speedup vs baseline: 1.2520x; 1.1051x over previous
#include <cuda_runtime.h>
#include <cuda_bf16.h>
#include <cuda_fp16.h>
#include <cstdint>

#define N_NODES 32768
#define N_EDGES 65536
#define HID 64
#define LN_EPS 1e-5f

// ---------------- scratch (static device globals; no allocation) ----------------
__device__ float g_sum1[N_NODES * HID];
__device__ float g_sum2[N_NODES * HID];
__device__ float g_cnt[N_NODES];
__device__ float g_h1[N_NODES * HID];
__device__ int   g_src[N_EDGES];
__device__ int   g_dst[N_EDGES];
// layer-2 weights fp16 transposed: [k=0..128][o][i] packed half2 (i even/odd):
// g_Wh[k*2048 + o*32 + i/2]; k==128 -> bias b2 (layer-2).
__device__ uint32_t g_Wh[129 * 2048];
// layer-1 w2 fp16: chunk i (=input channel): g_Wh1[i*2048 + o*32 + k/2]
__device__ uint32_t g_Wh1[4 * 2048];

__device__ __forceinline__ int clamp_node(long long v) {
    return v < 0 ? 0 : (v >= N_NODES ? N_NODES - 1 : (int)v);
}

__device__ __forceinline__ uint32_t h2_pack(float v0, float v1) {
    __half2 h = __float22half2_rn(make_float2(v0, v1));
    return *reinterpret_cast<uint32_t*>(&h);
}
__device__ __forceinline__ void mma_f16(float* c,
        uint32_t a0, uint32_t a1, uint32_t a2, uint32_t a3,
        uint32_t b0, uint32_t b1) {
    asm volatile(
        "mma.sync.aligned.m16n8k16.row.col.f32.f16.f16.f32 "
        "{%0,%1,%2,%3}, {%4,%5,%6,%7}, {%8,%9}, {%0,%1,%2,%3};\n"
        : "+f"(c[0]), "+f"(c[1]), "+f"(c[2]), "+f"(c[3])
        : "r"(a0), "r"(a1), "r"(a2), "r"(a3), "r"(b0), "r"(b1));
}
__device__ __forceinline__ void mma_f16_zc(float* c,
        uint32_t a0, uint32_t a1, uint32_t a2, uint32_t a3,
        uint32_t b0, uint32_t b1) {
    asm volatile(
        "mma.sync.aligned.m16n8k16.row.col.f32.f16.f16.f32 "
        "{%0,%1,%2,%3}, {%4,%5,%6,%7}, {%8,%9}, {%10,%11,%12,%13};\n"
        : "=f"(c[0]), "=f"(c[1]), "=f"(c[2]), "=f"(c[3])
        : "r"(a0), "r"(a1), "r"(a2), "r"(a3), "r"(b0), "r"(b1),
          "f"(0.f), "f"(0.f), "f"(0.f), "f"(0.f));
}
__device__ __forceinline__ void ldsm_x4(uint32_t& r0, uint32_t& r1,
                                        uint32_t& r2, uint32_t& r3, uint32_t saddr) {
    asm volatile("ldmatrix.sync.aligned.m8n8.x4.shared.b16 {%0,%1,%2,%3}, [%4];\n"
        : "=r"(r0), "=r"(r1), "=r"(r2), "=r"(r3) : "r"(saddr));
}
__device__ __forceinline__ uint32_t smem_u32(const void* p) {
    uint32_t a;
    asm("{ .reg .u64 t; cvta.to.shared.u64 t, %1; cvt.u32.u64 %0, t; }" : "=r"(a) : "l"(p));
    return a;
}
__device__ __forceinline__ void cp_async16(uint32_t dst_s, const void* src_g) {
    asm volatile("cp.async.cg.shared.global [%0], [%1], 16;"
                 :: "r"(dst_s), "l"(src_g) : "memory");
}
// vectorized no-return atomic add of 2 consecutive floats (sm_90+)
__device__ __forceinline__ void red_add2(float* addr, float v0, float v1) {
    asm volatile("red.global.add.v2.f32 [%0], {%1, %2};"
                 :: "l"(addr), "f"(v0), "f"(v1) : "memory");
}

// ---------------- kernel 0 (fused): zero + edge prep + w2(l2) + w2(l1) pack ----
#define ZB 8192
#define PB 256
#define SB_BLK 129
#define SB1_BLK 4
__global__ void fused_prep(const void* __restrict__ eidx_raw,
                           const float* __restrict__ w2,    // e2_w2 [128,4096]
                           const float* __restrict__ b2,    // [4096]
                           const float* __restrict__ w2l1,  // e1_w2 [64,256]
                           float* __restrict__ out) {
    int b = blockIdx.x, tid = threadIdx.x;
    if (b < ZB) {
        int idx = b * 256 + tid;
        g_sum1[idx] = 0.f; g_sum2[idx] = 0.f;
        if (idx < N_NODES) g_cnt[idx] = 0.f;
        if (idx < HID) out[idx] = 0.f;
    } else if (b < ZB + PB) {
        const long long* p64 = (const long long*)eidx_raw;
        const int*       p32 = (const int*)eidx_raw;
        bool is64 = true;
#pragma unroll
        for (int i = 0; i < 8; i++) {
            long long v = p64[i];
            if (v < 0 || v >= N_NODES) { is64 = false; break; }
        }
        int e = (b - ZB) * 256 + tid;
        long long s, d;
        if (is64) { s = p64[e]; d = p64[N_EDGES + e]; }
        else      { s = p32[e]; d = p32[N_EDGES + e]; }
        g_src[e] = clamp_node(s);
        g_dst[e] = clamp_node(d);
    } else if (b < ZB + PB + SB_BLK) {
        int k = b - ZB - PB;
        int o = tid & 63;
        int q = tid >> 6;
        const float* src = (k < 128) ? (w2 + (size_t)k * 4096) : b2;
        size_t base = (size_t)k * 2048 + o * 32;
#pragma unroll
        for (int jj = 0; jj < 8; jj++) {
            int j = q * 8 + jj;
            float v0 = __ldg(&src[(2 * j) * 64 + o]);
            float v1 = __ldg(&src[(2 * j + 1) * 64 + o]);
            g_Wh[base + j] = h2_pack(v0, v1);
        }
    } else {
        int i = b - ZB - PB - SB_BLK;     // input-channel chunk 0..3
        int o = tid & 63;
        int q = tid >> 6;
        size_t base = (size_t)i * 2048 + o * 32;
#pragma unroll
        for (int jj = 0; jj < 8; jj++) {
            int j = q * 8 + jj;           // k-pair index (hidden dim)
            float v0 = __ldg(&w2l1[(2 * j) * 256 + i * 64 + o]);
            float v1 = __ldg(&w2l1[(2 * j + 1) * 256 + i * 64 + o]);
            g_Wh1[base + j] = h2_pack(v0, v1);
        }
    }
}

// ---------------- kernel 1: layer-1 edge pipeline on tensor cores ---------------
__global__ void __launch_bounds__(128, 3) edge_l1_tc(
        const float* __restrict__ x,
        const float* __restrict__ ea,
        const float* __restrict__ w1,   // e1_w1 [4,64]
        const float* __restrict__ b1,   // [64]
        const float* __restrict__ b2) { // [256]
    __shared__ uint32_t SB1[4][2048];   // 32 KB (4 chunks x 8 KB)
    __shared__ float w1s[256];
    __shared__ float b1s[64];
    __shared__ float b2s[256];
    __shared__ int   dst_s[128];

    int tid = threadIdx.x;
    int eb  = blockIdx.x * 128;
    uint32_t sbase = smem_u32(&SB1[0][0]);

#pragma unroll
    for (int i = 0; i < 4; i++) {
        const uint32_t* gW = g_Wh1 + (size_t)i * 2048;
#pragma unroll
        for (int q = 0; q < 4; q++) {
            int u = tid * 4 + q;
            int o = u >> 3, ch = u & 7;
            cp_async16(sbase + (uint32_t)i * 8192
                       + (uint32_t)(o * 32 + ((ch ^ (o & 7)) << 2)) * 4,
                       gW + u * 4);
        }
    }
    asm volatile("cp.async.commit_group;" ::: "memory");

    w1s[tid] = __ldg(&w1[tid]);
    w1s[128 + tid] = __ldg(&w1[128 + tid]);
    if (tid < 64) b1s[tid] = __ldg(&b1[tid]);
    b2s[tid] = __ldg(&b2[tid]);
    b2s[128 + tid] = __ldg(&b2[128 + tid]);
    dst_s[tid] = g_dst[eb + tid];

    int lane = tid & 31, gID = lane >> 2, tig = lane & 3;
    int wb = (tid >> 5) * 32;
    int er[4] = {wb + gID, wb + 8 + gID, wb + 16 + gID, wb + 24 + gID};

    float4 aev[4];
    float  xsf[4][4];
#pragma unroll
    for (int j = 0; j < 4; j++) {
        aev[j] = __ldg((const float4*)(ea + (size_t)(eb + er[j]) * 4));
        float4 xv = __ldg((const float4*)(x + (size_t)g_src[eb + er[j]] * 4));
        xsf[j][0] = xv.x; xsf[j][1] = xv.y; xsf[j][2] = xv.z; xsf[j][3] = xv.w;
    }

    asm volatile("cp.async.wait_group 0;" ::: "memory");
    __syncthreads();

    uint32_t A1[2][4][4];
#pragma unroll
    for (int blk = 0; blk < 2; blk++) {
        float4 eA = aev[blk * 2], eB = aev[blk * 2 + 1];
#pragma unroll
        for (int c = 0; c < 4; c++) {
            int k0 = c * 16 + 2 * tig;
            float hA0, hA1, hA2, hA3, hB0, hB1, hB2, hB3;
#define H1F(a, k) fmaxf(b1s[k] + (a).x * w1s[k] + (a).y * w1s[64 + (k)] \
                        + (a).z * w1s[128 + (k)] + (a).w * w1s[192 + (k)], 0.f)
            hA0 = H1F(eA, k0);     hA1 = H1F(eA, k0 + 1);
            hB0 = H1F(eB, k0);     hB1 = H1F(eB, k0 + 1);
            hA2 = H1F(eA, k0 + 8); hA3 = H1F(eA, k0 + 9);
            hB2 = H1F(eB, k0 + 8); hB3 = H1F(eB, k0 + 9);
#undef H1F
            A1[blk][c][0] = h2_pack(hA0, hA1);
            A1[blk][c][1] = h2_pack(hB0, hB1);
            A1[blk][c][2] = h2_pack(hA2, hA3);
            A1[blk][c][3] = h2_pack(hB2, hB3);
        }
    }

    int lm_m = lane >> 3, lm_r = lane & 7;

    float acc[2][8][4];
#pragma unroll
    for (int blk = 0; blk < 2; blk++)
#pragma unroll
        for (int nt = 0; nt < 8; nt++)
#pragma unroll
            for (int q = 0; q < 4; q++) acc[blk][nt][q] = 0.f;

#pragma unroll
    for (int i = 0; i < 4; i++) {
        uint32_t bh = sbase + (uint32_t)i * 8192;
        float hv[4] = {xsf[0][i], xsf[1][i], xsf[2][i], xsf[3][i]};

#pragma unroll
        for (int ntp = 0; ntp < 4; ntp++) {
            float p0e[4], p0o[4], p1e[4], p1o[4];
#pragma unroll
            for (int c = 0; c < 4; c++) {
                int o  = (ntp * 2 + (lm_m >> 1)) * 8 + lm_r;
                int ch = c * 2 + (lm_m & 1);
                uint32_t off = (uint32_t)(o * 32 + ((ch ^ (o & 7)) << 2)) << 2;
                uint32_t r0, r1, r2, r3;
                ldsm_x4(r0, r1, r2, r3, bh + off);
                if (c == 0) {
                    mma_f16_zc(p0e, A1[0][0][0], A1[0][0][1], A1[0][0][2], A1[0][0][3], r0, r1);
                    mma_f16_zc(p0o, A1[0][0][0], A1[0][0][1], A1[0][0][2], A1[0][0][3], r2, r3);
                    mma_f16_zc(p1e, A1[1][0][0], A1[1][0][1], A1[1][0][2], A1[1][0][3], r0, r1);
                    mma_f16_zc(p1o, A1[1][0][0], A1[1][0][1], A1[1][0][2], A1[1][0][3], r2, r3);
                } else {
                    mma_f16(p0e, A1[0][c][0], A1[0][c][1], A1[0][c][2], A1[0][c][3], r0, r1);
                    mma_f16(p0o, A1[0][c][0], A1[0][c][1], A1[0][c][2], A1[0][c][3], r2, r3);
                    mma_f16(p1e, A1[1][c][0], A1[1][c][1], A1[1][c][2], A1[1][c][3], r0, r1);
                    mma_f16(p1o, A1[1][c][0], A1[1][c][1], A1[1][c][2], A1[1][c][3], r2, r3);
                }
            }
            int nt = ntp * 2;
            acc[0][nt][0]     = fmaf(hv[0], p0e[0], acc[0][nt][0]);
            acc[0][nt][1]     = fmaf(hv[0], p0e[1], acc[0][nt][1]);
            acc[0][nt][2]     = fmaf(hv[1], p0e[2], acc[0][nt][2]);
            acc[0][nt][3]     = fmaf(hv[1], p0e[3], acc[0][nt][3]);
            acc[0][nt + 1][0] = fmaf(hv[0], p0o[0], acc[0][nt + 1][0]);
            acc[0][nt + 1][1] = fmaf(hv[0], p0o[1], acc[0][nt + 1][1]);
            acc[0][nt + 1][2] = fmaf(hv[1], p0o[2], acc[0][nt + 1][2]);
            acc[0][nt + 1][3] = fmaf(hv[1], p0o[3], acc[0][nt + 1][3]);
            acc[1][nt][0]     = fmaf(hv[2], p1e[0], acc[1][nt][0]);
            acc[1][nt][1]     = fmaf(hv[2], p1e[1], acc[1][nt][1]);
            acc[1][nt][2]     = fmaf(hv[3], p1e[2], acc[1][nt][2]);
            acc[1][nt][3]     = fmaf(hv[3], p1e[3], acc[1][nt][3]);
            acc[1][nt + 1][0] = fmaf(hv[2], p1o[0], acc[1][nt + 1][0]);
            acc[1][nt + 1][1] = fmaf(hv[2], p1o[1], acc[1][nt + 1][1]);
            acc[1][nt + 1][2] = fmaf(hv[3], p1o[2], acc[1][nt + 1][2]);
            acc[1][nt + 1][3] = fmaf(hv[3], p1o[3], acc[1][nt + 1][3]);
        }
    }

    // epilogue: bias term + vectorized scatter (red.v2) + degree count
#pragma unroll
    for (int blk = 0; blk < 2; blk++) {
        int jA = blk * 2, jB = blk * 2 + 1;
        int dA = dst_s[er[jA]], dB = dst_s[er[jB]];
#pragma unroll
        for (int nt = 0; nt < 8; nt++) {
            int o = nt * 8 + 2 * tig;
#define BSUM(j, oo) (xsf[j][0] * b2s[oo] + xsf[j][1] * b2s[64 + (oo)] \
                     + xsf[j][2] * b2s[128 + (oo)] + xsf[j][3] * b2s[192 + (oo)])
            red_add2(&g_sum1[(size_t)dA * HID + o],
                     acc[blk][nt][0] + BSUM(jA, o), acc[blk][nt][1] + BSUM(jA, o + 1));
            red_add2(&g_sum1[(size_t)dB * HID + o],
                     acc[blk][nt][2] + BSUM(jB, o), acc[blk][nt][3] + BSUM(jB, o + 1));
#undef BSUM
        }
    }
    if (tig == 0) {
#pragma unroll
        for (int j = 0; j < 4; j++) atomicAdd(&g_cnt[dst_s[er[j]]], 1.f);
    }
}

// ---------------- kernel 2: layer-1 node update ----------------
__global__ void node_l1_kernel(const float* __restrict__ x,
                               const float* __restrict__ root1,
                               const float* __restrict__ bias1,
                               const float* __restrict__ lng,
                               const float* __restrict__ lnb) {
    int warp = (blockIdx.x * blockDim.x + threadIdx.x) >> 5;
    int lane = threadIdx.x & 31;
    int n = warp;
    if (n >= N_NODES) return;

    float inv = 1.f / fmaxf(g_cnt[n], 1.f);
    float4 xv = __ldg((const float4*)(x + (size_t)n * 4));
    float z0 = g_sum1[(size_t)n * HID + lane] * inv + __ldg(&bias1[lane])
             + xv.x * __ldg(&root1[lane])       + xv.y * __ldg(&root1[64 + lane])
             + xv.z * __ldg(&root1[128 + lane]) + xv.w * __ldg(&root1[192 + lane]);
    float z1 = g_sum1[(size_t)n * HID + 32 + lane] * inv + __ldg(&bias1[32 + lane])
             + xv.x * __ldg(&root1[32 + lane])  + xv.y * __ldg(&root1[96 + lane])
             + xv.z * __ldg(&root1[160 + lane]) + xv.w * __ldg(&root1[224 + lane]);
    z0 = fmaxf(z0, 0.f);
    z1 = fmaxf(z1, 0.f);

    float s = z0 + z1;
#pragma unroll
    for (int o = 16; o; o >>= 1) s += __shfl_xor_sync(0xffffffffu, s, o);
    float m = s * (1.f / 64.f);
    float d0 = z0 - m, d1 = z1 - m;
    float v = d0 * d0 + d1 * d1;
#pragma unroll
    for (int o = 16; o; o >>= 1) v += __shfl_xor_sync(0xffffffffu, v, o);
    v *= (1.f / 64.f);
    float is = rsqrtf(v + LN_EPS);
    g_h1[(size_t)n * HID + lane]      = d0 * is * __ldg(&lng[lane])      + __ldg(&lnb[lane]);
    g_h1[(size_t)n * HID + 32 + lane] = d1 * is * __ldg(&lng[32 + lane]) + __ldg(&lnb[32 + lane]);
}

// ---------------- kernel 3: layer-2 tensor-core kernel (R13 v9 + red.v2) --------
__global__ void __launch_bounds__(128, 3) edge_l2_tc(
        const float* __restrict__ ea,
        const float* __restrict__ w1,   // e2_w1 [4,128]
        const float* __restrict__ b1) { // [128]
    __shared__ uint32_t SBUF[4][2048];   // 4 tile slots x 8 KB = 32 KB
    __shared__ float w1s[512];
    __shared__ float b1s[128];
    __shared__ int   dst_s[128];

    int tid = threadIdx.x;
    int tile = blockIdx.x >> 1;
    int half = blockIdx.x & 1;
    int eb   = tile * 128;
    int k0   = half * 64;
    int kend = half ? 128 : 63;

#pragma unroll
    for (int q = 0; q < 4; q++) w1s[tid + q * 128] = __ldg(&w1[tid + q * 128]);
    b1s[tid] = __ldg(&b1[tid]);
    dst_s[tid] = g_dst[eb + tid];

    int lane = tid & 31, gID = lane >> 2, tig = lane & 3;
    int wb = (tid >> 5) * 32;
    int er[4] = {wb + gID, wb + 8 + gID, wb + 16 + gID, wb + 24 + gID};

    uint32_t sbase = smem_u32(&SBUF[0][0]);

    uint32_t st_off[4];
#pragma unroll
    for (int q = 0; q < 4; q++) {
        int u = tid * 4 + q;
        int o = u >> 3, ch = u & 7;
        st_off[q] = (uint32_t)(o * 32 + ((ch ^ (o & 7)) << 2)) * 4;
    }

    // prologue: stage tiles k0, k0+1 into slots 0,1
#pragma unroll
    for (int t = 0; t < 2; t++) {
        const uint32_t* gW = g_Wh + (size_t)(k0 + t) * 2048;
#pragma unroll
        for (int q = 0; q < 4; q++)
            cp_async16(sbase + (uint32_t)t * 8192 + st_off[q], gW + (tid * 4 + q) * 4);
    }
    asm volatile("cp.async.commit_group;" ::: "memory");

    // gather H1[src] -> registers as single fp16 (overlaps cp.async)
    uint32_t A[2][4][4];
#pragma unroll
    for (int blk = 0; blk < 2; blk++) {
        const float* rA = g_h1 + (size_t)g_src[eb + er[blk * 2]] * HID;
        const float* rB = g_h1 + (size_t)g_src[eb + er[blk * 2 + 1]] * HID;
#pragma unroll
        for (int c = 0; c < 4; c++) {
            int i0 = c * 16 + 2 * tig;
            float2 x0 = __ldg((const float2*)(rA + i0));
            float2 x1 = __ldg((const float2*)(rB + i0));
            float2 x2 = __ldg((const float2*)(rA + i0 + 8));
            float2 x3 = __ldg((const float2*)(rB + i0 + 8));
            A[blk][c][0] = h2_pack(x0.x, x0.y);
            A[blk][c][1] = h2_pack(x1.x, x1.y);
            A[blk][c][2] = h2_pack(x2.x, x2.y);
            A[blk][c][3] = h2_pack(x3.x, x3.y);
        }
    }
    float4 aev[4];
#pragma unroll
    for (int j = 0; j < 4; j++)
        aev[j] = __ldg((const float4*)(ea + (size_t)(eb + er[j]) * 4));

    asm volatile("cp.async.wait_group 0;" ::: "memory");
    __syncthreads();

    int lm_m = lane >> 3, lm_r = lane & 7;

    float acc[2][8][4];
#pragma unroll
    for (int blk = 0; blk < 2; blk++)
#pragma unroll
        for (int nt = 0; nt < 8; nt++)
#pragma unroll
            for (int q = 0; q < 4; q++) acc[blk][nt][q] = 0.f;

    for (int kk = k0; kk <= kend; kk += 2) {
        int pair = ((kk - k0) >> 1) & 1;

#pragma unroll
        for (int t = 0; t < 2; t++) {
            int kn = kk + 2 + t;
            if (kn <= kend) {
                const uint32_t* gW = g_Wh + (size_t)kn * 2048;
                uint32_t dbase = sbase + (uint32_t)((pair ^ 1) * 2 + t) * 8192;
#pragma unroll
                for (int q = 0; q < 4; q++)
                    cp_async16(dbase + st_off[q], gW + (tid * 4 + q) * 4);
            }
        }
        asm volatile("cp.async.commit_group;" ::: "memory");

#pragma unroll
        for (int t = 0; t < 2; t++) {
            int k = kk + t;
            if (k > kend) break;
            uint32_t bh = sbase + (uint32_t)(pair * 2 + t) * 8192;

            float hv[4];
            if (k < 128) {
                float c0 = w1s[k], c1 = w1s[128 + k], c2 = w1s[256 + k], c3 = w1s[384 + k];
                float bb = b1s[k];
#pragma unroll
                for (int j = 0; j < 4; j++)
                    hv[j] = fmaxf(fmaf(aev[j].w, c3, fmaf(aev[j].z, c2,
                                  fmaf(aev[j].y, c1, fmaf(aev[j].x, c0, bb)))), 0.f);
            } else { hv[0] = hv[1] = hv[2] = hv[3] = 1.f; }

#pragma unroll
            for (int ntp = 0; ntp < 4; ntp++) {
                float p0e[4], p0o[4], p1e[4], p1o[4];
#pragma unroll
                for (int c = 0; c < 4; c++) {
                    int o  = (ntp * 2 + (lm_m >> 1)) * 8 + lm_r;
                    int ch = c * 2 + (lm_m & 1);
                    uint32_t off = (uint32_t)(o * 32 + ((ch ^ (o & 7)) << 2)) << 2;
                    uint32_t r0, r1, r2, r3;
                    ldsm_x4(r0, r1, r2, r3, bh + off);
                    if (c == 0) {
                        mma_f16_zc(p0e, A[0][0][0], A[0][0][1], A[0][0][2], A[0][0][3], r0, r1);
                        mma_f16_zc(p0o, A[0][0][0], A[0][0][1], A[0][0][2], A[0][0][3], r2, r3);
                        mma_f16_zc(p1e, A[1][0][0], A[1][0][1], A[1][0][2], A[1][0][3], r0, r1);
                        mma_f16_zc(p1o, A[1][0][0], A[1][0][1], A[1][0][2], A[1][0][3], r2, r3);
                    } else {
                        mma_f16(p0e, A[0][c][0], A[0][c][1], A[0][c][2], A[0][c][3], r0, r1);
                        mma_f16(p0o, A[0][c][0], A[0][c][1], A[0][c][2], A[0][c][3], r2, r3);
                        mma_f16(p1e, A[1][c][0], A[1][c][1], A[1][c][2], A[1][c][3], r0, r1);
                        mma_f16(p1o, A[1][c][0], A[1][c][1], A[1][c][2], A[1][c][3], r2, r3);
                    }
                }
                int nt = ntp * 2;
                acc[0][nt][0]     = fmaf(hv[0], p0e[0], acc[0][nt][0]);
                acc[0][nt][1]     = fmaf(hv[0], p0e[1], acc[0][nt][1]);
                acc[0][nt][2]     = fmaf(hv[1], p0e[2], acc[0][nt][2]);
                acc[0][nt][3]     = fmaf(hv[1], p0e[3], acc[0][nt][3]);
                acc[0][nt + 1][0] = fmaf(hv[0], p0o[0], acc[0][nt + 1][0]);
                acc[0][nt + 1][1] = fmaf(hv[0], p0o[1], acc[0][nt + 1][1]);
                acc[0][nt + 1][2] = fmaf(hv[1], p0o[2], acc[0][nt + 1][2]);
                acc[0][nt + 1][3] = fmaf(hv[1], p0o[3], acc[0][nt + 1][3]);
                acc[1][nt][0]     = fmaf(hv[2], p1e[0], acc[1][nt][0]);
                acc[1][nt][1]     = fmaf(hv[2], p1e[1], acc[1][nt][1]);
                acc[1][nt][2]     = fmaf(hv[3], p1e[2], acc[1][nt][2]);
                acc[1][nt][3]     = fmaf(hv[3], p1e[3], acc[1][nt][3]);
                acc[1][nt + 1][0] = fmaf(hv[2], p1o[0], acc[1][nt + 1][0]);
                acc[1][nt + 1][1] = fmaf(hv[2], p1o[1], acc[1][nt + 1][1]);
                acc[1][nt + 1][2] = fmaf(hv[3], p1o[2], acc[1][nt + 1][2]);
                acc[1][nt + 1][3] = fmaf(hv[3], p1o[3], acc[1][nt + 1][3]);
            }
        }

        asm volatile("cp.async.wait_group 0;" ::: "memory");
        __syncthreads();
    }

    // epilogue: vectorized scatter of partial messages (red.v2)
#pragma unroll
    for (int blk = 0; blk < 2; blk++) {
        int dA = dst_s[er[blk * 2]], dB = dst_s[er[blk * 2 + 1]];
#pragma unroll
        for (int nt = 0; nt < 8; nt++) {
            int o = nt * 8 + 2 * tig;
            red_add2(&g_sum2[(size_t)dA * HID + o], acc[blk][nt][0], acc[blk][nt][1]);
            red_add2(&g_sum2[(size_t)dB * HID + o], acc[blk][nt][2], acc[blk][nt][3]);
        }
    }
}

// ---------------- kernel 4: layer-2 node update + LN + global mean pool ------------
__global__ void node_l2_kernel(const float* __restrict__ root2,
                               const float* __restrict__ bias2,
                               const float* __restrict__ lng,
                               const float* __restrict__ lnb,
                               float* __restrict__ out) {
    __shared__ float rt[4096];
    __shared__ float acc[64];
    int tid = threadIdx.x;
#pragma unroll
    for (int q = 0; q < 16; q++) rt[tid + q * 256] = __ldg(&root2[tid + q * 256]);
    if (tid < 64) acc[tid] = 0.f;
    __syncthreads();

    int warp = tid >> 5, lane = tid & 31;
    int n = blockIdx.x * 8 + warp;

    float a0 = g_h1[(size_t)n * HID + lane];
    float a1 = g_h1[(size_t)n * HID + 32 + lane];
    float inv = 1.f / fmaxf(g_cnt[n], 1.f);
    float z0 = g_sum2[(size_t)n * HID + lane] * inv + __ldg(&bias2[lane]);
    float z1 = g_sum2[(size_t)n * HID + 32 + lane] * inv + __ldg(&bias2[32 + lane]);

#pragma unroll 16
    for (int i = 0; i < 64; i++) {
        float hi = __shfl_sync(0xffffffffu, (i < 32) ? a0 : a1, i & 31);
        z0 = fmaf(hi, rt[i * 64 + lane], z0);
        z1 = fmaf(hi, rt[i * 64 + 32 + lane], z1);
    }
    z0 = fmaxf(z0, 0.f);
    z1 = fmaxf(z1, 0.f);

    float s = z0 + z1;
#pragma unroll
    for (int o = 16; o; o >>= 1) s += __shfl_xor_sync(0xffffffffu, s, o);
    float m = s * (1.f / 64.f);
    float d0 = z0 - m, d1 = z1 - m;
    float v = d0 * d0 + d1 * d1;
#pragma unroll
    for (int o = 16; o; o >>= 1) v += __shfl_xor_sync(0xffffffffu, v, o);
    v *= (1.f / 64.f);
    float is = rsqrtf(v + LN_EPS);
    float y0 = d0 * is * __ldg(&lng[lane])      + __ldg(&lnb[lane]);
    float y1 = d1 * is * __ldg(&lng[32 + lane]) + __ldg(&lnb[32 + lane]);

    atomicAdd(&acc[lane],      y0 * (1.f / (float)N_NODES));
    atomicAdd(&acc[32 + lane], y1 * (1.f / (float)N_NODES));
    __syncthreads();
    if (tid < 64) atomicAdd(&out[tid], acc[tid]);
}

// ---------------- launch: robust input-order resolution ----------------
static const int EXP_SIZE[20] = {
    131072, 262144, 131072, 32768, 256, 64, 16384, 256, 256, 64, 64, 64,
    512, 128, 524288, 4096, 4096, 64, 64, 64};

static const int PERM_DICT[20]  = {0,1,2,3,4,5,6,7,8,9,10,11,12,13,14,15,16,17,18,19};
static const int PERM_SIG[20]   = {0,1,18,19,2,3,4,5,6,7,8,9,10,11,12,13,14,15,16,17};
static const int PERM_ALPHA[20] = {19,11,12,0,5,3,6,4,17,1,14,13,9,7,10,8,18,2,16,15};

extern "C" void kernel_launch(void* const* d_in, const int* in_sizes, int n_in,
                              void* d_out, int out_size) {
    const int* perm = PERM_DICT;
    const int* cands[3] = {PERM_DICT, PERM_SIG, PERM_ALPHA};
    for (int p = 0; p < 3; p++) {
        bool ok = (n_in >= 20);
        for (int c = 0; ok && c < 20; c++)
            if (in_sizes[cands[p][c]] != EXP_SIZE[c]) ok = false;
        if (ok) { perm = cands[p]; break; }
    }

    const float* x    = (const float*)d_in[perm[0]];
    const float* ea   = (const float*)d_in[perm[1]];
    const void*  eidx = d_in[perm[2]];
    const float* e1_w1 = (const float*)d_in[perm[4]];
    const float* e1_b1 = (const float*)d_in[perm[5]];
    const float* e1_w2 = (const float*)d_in[perm[6]];
    const float* e1_b2 = (const float*)d_in[perm[7]];
    const float* root1 = (const float*)d_in[perm[8]];
    const float* bias1 = (const float*)d_in[perm[9]];
    const float* ln1_g = (const float*)d_in[perm[10]];
    const float* ln1_b = (const float*)d_in[perm[11]];
    const float* e2_w1 = (const float*)d_in[perm[12]];
    const float* e2_b1 = (const float*)d_in[perm[13]];
    const float* e2_w2 = (const float*)d_in[perm[14]];
    const float* e2_b2 = (const float*)d_in[perm[15]];
    const float* root2 = (const float*)d_in[perm[16]];
    const float* bias2 = (const float*)d_in[perm[17]];
    const float* ln2_g = (const float*)d_in[perm[18]];
    const float* ln2_b = (const float*)d_in[perm[19]];
    float* out = (float*)d_out;

    fused_prep<<<ZB + PB + SB_BLK + SB1_BLK, 256>>>(eidx, e2_w2, e2_b2, e1_w2, out);
    edge_l1_tc<<<N_EDGES / 128, 128>>>(x, ea, e1_w1, e1_b1, e1_b2);
    node_l1_kernel<<<N_NODES / 8, 256>>>(x, root1, bias1, ln1_g, ln1_b);
    edge_l2_tc<<<2 * (N_EDGES / 128), 128>>>(ea, e2_w1, e2_b1);
    node_l2_kernel<<<N_NODES / 8, 256>>>(root2, bias2, ln2_g, ln2_b, out);
}